// round 16
// baseline (speedup 1.0000x reference)
#include <cuda_runtime.h>
#include <cuda_fp16.h>
#include <math.h>

#define Bb 64
#define Nn 1024
#define DEG 8
#define ALPHA 0.2f

// Scratch (static __device__ globals — allocation-free per harness rules)
__device__ float g_s1[Bb * Nn];                         // h @ a1 (fp32)
__device__ float g_s2[Bb * Nn];                         // h @ a2 (fp32)
__device__ __align__(16) float   g_w[Bb * Nn * DEG];    // normalized softmax weights
__device__ __align__(16) __half2 g_h2[Bb * Nn * 32];    // 8 MB: h in fp16 (gather operand)

__device__ __forceinline__ unsigned h2u(__half2 v) {
    return *reinterpret_cast<unsigned*>(&v);
}

// ---------------------------------------------------------------------------
// Kernel 1: h = atoms @ W, scalar FFMA, 8x8 per thread — 64-thread CTAs over
// 64 rows, grid 1024. 32 KB smem/CTA -> up to 7 CTAs/SM: the WHOLE grid is
// resident in one wave (1024 <= 148*7), killing the 2-CTA wave quantization
// that pinned the 256-row variant at 20.0us (floor 15.7).
// A tile: float4-XOR swizzle [k][g4 ^ (k&15)] = exactly 16 KB, conflict-free
// mainloop loads. Inner loop per k: 4 LDS.128 + 64 FFMA (the proven 16:1).
// Epilogue: fp16 h store (coalesced uint4) + fused s1/s2 (8-lane butterfly).
// ---------------------------------------------------------------------------
__global__ __launch_bounds__(64) void gat_gemm(const float* __restrict__ atoms,
                                               const float* __restrict__ W,
                                               const float* __restrict__ a)
{
    extern __shared__ __align__(16) float sm[];
    float4* sA4 = (float4*)sm;             // [64 k][16 g4] XOR-swizzled, 16 KB
    float*  sW  = sm + 64 * 16 * 4;        // [64 k][64 c], 16 KB

    const int tid  = threadIdx.x;          // 0..63
    const int row0 = blockIdx.x * 64;

    // W: 1024 float4, coalesced
    #pragma unroll
    for (int i = tid; i < 1024; i += 64) ((float4*)sW)[i] = ((const float4*)W)[i];

    // A: thread owns k = tid; gmem reads coalesced across tid; swizzled store.
    {
        const int kq = tid & 15;
        #pragma unroll 8
        for (int j = 0; j < 64; j++) {
            const float v = atoms[(size_t)(row0 + j) * 64 + tid];
            ((float*)&sA4[tid * 16 + ((j >> 2) ^ kq)])[j & 3] = v;
        }
    }
    __syncthreads();

    const int cg = tid & 7;    // col group: cols 8*cg..+7
    const int rg = tid >> 3;   // row group: rows 8*rg..+7 (0..7)

    float acc[8][8];
    #pragma unroll
    for (int r = 0; r < 8; r++)
        #pragma unroll
        for (int c = 0; c < 8; c++) acc[r][c] = 0.f;

    #pragma unroll 4
    for (int k = 0; k < 64; k++) {
        const int ks = k & 15;
        float4 a0 = sA4[k * 16 + ((rg * 2)     ^ ks)];   // rows rg*8..+3
        float4 a1 = sA4[k * 16 + ((rg * 2 + 1) ^ ks)];   // rows rg*8+4..+7
        const float* Wk = &sW[k * 64 + cg * 8];
        float4 w0 = *(const float4*)(Wk);
        float4 w1 = *(const float4*)(Wk + 4);
        float ar[8] = {a0.x, a0.y, a0.z, a0.w, a1.x, a1.y, a1.z, a1.w};
        float wr[8] = {w0.x, w0.y, w0.z, w0.w, w1.x, w1.y, w1.z, w1.w};
        #pragma unroll
        for (int r = 0; r < 8; r++)
            #pragma unroll
            for (int c = 0; c < 8; c++)
                acc[r][c] = fmaf(ar[r], wr[c], acc[r][c]);
    }

    float a1v[8], a2v[8];
    #pragma unroll
    for (int c = 0; c < 8; c++) {
        a1v[c] = a[cg * 8 + c];
        a2v[c] = a[64 + cg * 8 + c];
    }

    #pragma unroll
    for (int r = 0; r < 8; r++) {
        const int row = row0 + rg * 8 + r;

        uint4 pk;
        pk.x = h2u(__floats2half2_rn(acc[r][0], acc[r][1]));
        pk.y = h2u(__floats2half2_rn(acc[r][2], acc[r][3]));
        pk.z = h2u(__floats2half2_rn(acc[r][4], acc[r][5]));
        pk.w = h2u(__floats2half2_rn(acc[r][6], acc[r][7]));
        *reinterpret_cast<uint4*>(&g_h2[(size_t)row * 32 + cg * 4]) = pk;

        float p1 = 0.f, p2 = 0.f;
        #pragma unroll
        for (int c = 0; c < 8; c++) {
            p1 = fmaf(acc[r][c], a1v[c], p1);
            p2 = fmaf(acc[r][c], a2v[c], p2);
        }
        #pragma unroll
        for (int off = 4; off > 0; off >>= 1) {
            p1 += __shfl_xor_sync(0xffffffffu, p1, off);
            p2 += __shfl_xor_sync(0xffffffffu, p2, off);
        }
        if (cg == 0) {
            g_s1[row] = p1;
            g_s2[row] = p2;
        }
    }
}

// ---------------------------------------------------------------------------
// Kernel 2 (R13, proven): per-row softmax weights, one thread per row.
// ---------------------------------------------------------------------------
__global__ __launch_bounds__(256) void gat_weights(const int* __restrict__ edges)
{
    const int g = blockIdx.x * 256 + threadIdx.x;
    const int b = g >> 10;
    const float* s2b = g_s2 + (b << 10);

    const int4 ea = __ldg(&((const int4*)edges)[2 * g]);
    const int4 eb = __ldg(&((const int4*)edges)[2 * g + 1]);
    int e[DEG] = { ea.x & (Nn - 1), ea.y & (Nn - 1), ea.z & (Nn - 1), ea.w & (Nn - 1),
                   eb.x & (Nn - 1), eb.y & (Nn - 1), eb.z & (Nn - 1), eb.w & (Nn - 1) };

    const float s1g = g_s1[g];

    float w[DEG];
    float mx = -1e30f;
    #pragma unroll
    for (int m = 0; m < DEG; m++) {
        float ev = s1g + __ldg(&s2b[e[m]]);
        ev = ev > 0.f ? ev : ALPHA * ev;
        bool dup = false;
        #pragma unroll
        for (int n = 0; n < m; n++) dup = dup || (e[n] == e[m]);
        w[m] = dup ? -1e30f : ev;
        mx = fmaxf(mx, w[m]);
    }
    float den = 0.f;
    #pragma unroll
    for (int m = 0; m < DEG; m++) {
        w[m] = (w[m] == -1e30f) ? 0.f : __expf(w[m] - mx);
        den += w[m];
    }
    const float inv = 1.f / den;

    ((float4*)g_w)[2 * g]     = make_float4(w[0] * inv, w[1] * inv, w[2] * inv, w[3] * inv);
    ((float4*)g_w)[2 * g + 1] = make_float4(w[4] * inv, w[5] * inv, w[6] * inv, w[7] * inv);
}

// ---------------------------------------------------------------------------
// Kernel 3 (R13, proven): aggregation, two rows per warp (16 gathers in flight).
// ---------------------------------------------------------------------------
__global__ __launch_bounds__(256) void gat_agg(const int* __restrict__ edges,
                                               float* __restrict__ out)
{
    const int wid  = (blockIdx.x * 256 + threadIdx.x) >> 5;
    const int lane = threadIdx.x & 31;
    const int g0   = wid * 2;
    const int b    = g0 >> 10;

    const __half2* hb = g_h2 + ((size_t)b << 15);

    const float4 wa0 = __ldg(&((const float4*)g_w)[2 * g0]);
    const float4 wb0 = __ldg(&((const float4*)g_w)[2 * g0 + 1]);
    const float4 wa1 = __ldg(&((const float4*)g_w)[2 * g0 + 2]);
    const float4 wb1 = __ldg(&((const float4*)g_w)[2 * g0 + 3]);
    const int4 ea0 = __ldg(&((const int4*)edges)[2 * g0]);
    const int4 eb0 = __ldg(&((const int4*)edges)[2 * g0 + 1]);
    const int4 ea1 = __ldg(&((const int4*)edges)[2 * g0 + 2]);
    const int4 eb1 = __ldg(&((const int4*)edges)[2 * g0 + 3]);

    float2 acc0 = make_float2(0.f, 0.f);
    float2 acc1 = make_float2(0.f, 0.f);
    #define GSTEP(ACC, E, Wv) { \
        const float2 hv = __half22float2(__ldg(&hb[(size_t)((E) & (Nn - 1)) * 32 + lane])); \
        ACC.x = fmaf((Wv), hv.x, ACC.x); \
        ACC.y = fmaf((Wv), hv.y, ACC.y); }
    GSTEP(acc0, ea0.x, wa0.x) GSTEP(acc1, ea1.x, wa1.x)
    GSTEP(acc0, ea0.y, wa0.y) GSTEP(acc1, ea1.y, wa1.y)
    GSTEP(acc0, ea0.z, wa0.z) GSTEP(acc1, ea1.z, wa1.z)
    GSTEP(acc0, ea0.w, wa0.w) GSTEP(acc1, ea1.w, wa1.w)
    GSTEP(acc0, eb0.x, wb0.x) GSTEP(acc1, eb1.x, wb1.x)
    GSTEP(acc0, eb0.y, wb0.y) GSTEP(acc1, eb1.y, wb1.y)
    GSTEP(acc0, eb0.z, wb0.z) GSTEP(acc1, eb1.z, wb1.z)
    GSTEP(acc0, eb0.w, wb0.w) GSTEP(acc1, eb1.w, wb1.w)
    #undef GSTEP

    float2 o0, o1;
    o0.x = acc0.x > 0.f ? acc0.x : (__expf(acc0.x) - 1.f);
    o0.y = acc0.y > 0.f ? acc0.y : (__expf(acc0.y) - 1.f);
    o1.x = acc1.x > 0.f ? acc1.x : (__expf(acc1.x) - 1.f);
    o1.y = acc1.y > 0.f ? acc1.y : (__expf(acc1.y) - 1.f);
    ((float2*)out)[(size_t)g0 * 32 + lane]       = o0;
    ((float2*)out)[(size_t)(g0 + 1) * 32 + lane] = o1;
}

// ---------------------------------------------------------------------------
extern "C" void kernel_launch(void* const* d_in, const int* in_sizes, int n_in,
                              void* d_out, int out_size) {
    // Bind inputs BY ELEMENT COUNT (all four sizes distinct) — order-proof.
    const float* atoms = nullptr;   // 64*1024*64 = 4194304 (f32)
    const int*   edges = nullptr;   // 64*1024*8  = 524288  (i32: jax x64 off)
    const float* W     = nullptr;   // 64*64      = 4096    (f32)
    const float* a     = nullptr;   // 2*64*1     = 128     (f32)

    for (int i = 0; i < n_in; i++) {
        switch (in_sizes[i]) {
            case 4194304: atoms = (const float*)d_in[i]; break;
            case 524288:  edges = (const int*)d_in[i];   break;
            case 4096:    W     = (const float*)d_in[i]; break;
            case 128:     a     = (const float*)d_in[i]; break;
            default: break;
        }
    }
    if (!atoms || !edges || !W || !a) return;

    float* out = (float*)d_out;

    const int smem = 32768;   // 16 KB A (swizzled) + 16 KB W
    cudaFuncSetAttribute(gat_gemm, cudaFuncAttributeMaxDynamicSharedMemorySize, smem);

    gat_gemm<<<(Bb * Nn) / 64, 64, smem>>>(atoms, W, a);
    gat_weights<<<(Bb * Nn) / 256, 256>>>(edges);
    gat_agg<<<(Bb * Nn) / 2 / 8, 256>>>(edges, out);
}

// round 17
// speedup vs baseline: 1.0580x; 1.0580x over previous
#include <cuda_runtime.h>
#include <cuda_fp16.h>
#include <math.h>

#define Bb 64
#define Nn 1024
#define DEG 8
#define ALPHA 0.2f

#define HALF_ROWS 32768   // 32 batches

// Scratch (static __device__ globals — allocation-free per harness rules)
__device__ float g_s1[Bb * Nn];                         // h @ a1 (fp32)
__device__ float g_s2[Bb * Nn];                         // h @ a2 (fp32)
__device__ __align__(16) float   g_w[Bb * Nn * DEG];    // normalized softmax weights
__device__ __align__(16) __half2 g_h2[Bb * Nn * 32];    // 8 MB: h in fp16 (gather operand)

#define SAT_PITCH 260   // floats; 16B-aligned rows, spreads banks

__device__ __forceinline__ unsigned h2u(__half2 v) {
    return *reinterpret_cast<unsigned*>(&v);
}

// ---------------------------------------------------------------------------
// Kernel 1 (R13 shape, proven 20.0us full-size): h = atoms @ W, scalar FFMA,
// 8x8 per thread, 256-row CTAs. Launched as TWO 128-CTA half-grids (batches
// 0-31 / 32-63) so the second half's FFMA work overlaps the first half's
// L2-bound tail kernels on another stream. rowOff selects the half.
// ---------------------------------------------------------------------------
__global__ __launch_bounds__(256) void gat_gemm(const float* __restrict__ atoms,
                                                const float* __restrict__ W,
                                                const float* __restrict__ a,
                                                int rowOff)
{
    extern __shared__ __align__(16) float sm[];
    float* sAT = sm;                       // [64 k][SAT_PITCH] (row-transposed atoms)
    float* sW  = sm + 64 * SAT_PITCH;      // [64 k][64 c]

    const int tid  = threadIdx.x;
    const int row0 = rowOff + blockIdx.x * 256;

    #pragma unroll
    for (int i = tid; i < 4096; i += 256) sW[i] = W[i];

    #pragma unroll
    for (int i = tid; i < 16384; i += 256) {
        int r = i >> 6, k = i & 63;
        sAT[k * SAT_PITCH + r] = atoms[(size_t)(row0 + r) * 64 + k];
    }
    __syncthreads();

    const int cg = tid & 7;    // col group: cols 8*cg..+7
    const int rg = tid >> 3;   // row group: rows 8*rg..+7

    float acc[8][8];
    #pragma unroll
    for (int r = 0; r < 8; r++)
        #pragma unroll
        for (int c = 0; c < 8; c++) acc[r][c] = 0.f;

    #pragma unroll 4
    for (int k = 0; k < 64; k++) {
        const float* Ak = &sAT[k * SAT_PITCH + rg * 8];
        const float* Wk = &sW[k * 64 + cg * 8];
        float4 a0 = *(const float4*)(Ak);
        float4 a1 = *(const float4*)(Ak + 4);
        float4 w0 = *(const float4*)(Wk);
        float4 w1 = *(const float4*)(Wk + 4);
        float ar[8] = {a0.x, a0.y, a0.z, a0.w, a1.x, a1.y, a1.z, a1.w};
        float wr[8] = {w0.x, w0.y, w0.z, w0.w, w1.x, w1.y, w1.z, w1.w};
        #pragma unroll
        for (int r = 0; r < 8; r++)
            #pragma unroll
            for (int c = 0; c < 8; c++)
                acc[r][c] = fmaf(ar[r], wr[c], acc[r][c]);
    }

    float a1v[8], a2v[8];
    #pragma unroll
    for (int c = 0; c < 8; c++) {
        a1v[c] = a[cg * 8 + c];
        a2v[c] = a[64 + cg * 8 + c];
    }

    #pragma unroll
    for (int r = 0; r < 8; r++) {
        const int row = row0 + rg * 8 + r;

        uint4 pk;
        pk.x = h2u(__floats2half2_rn(acc[r][0], acc[r][1]));
        pk.y = h2u(__floats2half2_rn(acc[r][2], acc[r][3]));
        pk.z = h2u(__floats2half2_rn(acc[r][4], acc[r][5]));
        pk.w = h2u(__floats2half2_rn(acc[r][6], acc[r][7]));
        *reinterpret_cast<uint4*>(&g_h2[(size_t)row * 32 + cg * 4]) = pk;

        float p1 = 0.f, p2 = 0.f;
        #pragma unroll
        for (int c = 0; c < 8; c++) {
            p1 = fmaf(acc[r][c], a1v[c], p1);
            p2 = fmaf(acc[r][c], a2v[c], p2);
        }
        #pragma unroll
        for (int off = 4; off > 0; off >>= 1) {
            p1 += __shfl_xor_sync(0xffffffffu, p1, off);
            p2 += __shfl_xor_sync(0xffffffffu, p2, off);
        }
        if (cg == 0) {
            g_s1[row] = p1;
            g_s2[row] = p2;
        }
    }
}

// ---------------------------------------------------------------------------
// Kernel 2 (R13, proven): per-row softmax weights, one thread per row.
// ---------------------------------------------------------------------------
__global__ __launch_bounds__(256) void gat_weights(const int* __restrict__ edges,
                                                   int rowOff)
{
    const int g = rowOff + blockIdx.x * 256 + threadIdx.x;
    const int b = g >> 10;
    const float* s2b = g_s2 + (b << 10);

    const int4 ea = __ldg(&((const int4*)edges)[2 * g]);
    const int4 eb = __ldg(&((const int4*)edges)[2 * g + 1]);
    int e[DEG] = { ea.x & (Nn - 1), ea.y & (Nn - 1), ea.z & (Nn - 1), ea.w & (Nn - 1),
                   eb.x & (Nn - 1), eb.y & (Nn - 1), eb.z & (Nn - 1), eb.w & (Nn - 1) };

    const float s1g = g_s1[g];

    float w[DEG];
    float mx = -1e30f;
    #pragma unroll
    for (int m = 0; m < DEG; m++) {
        float ev = s1g + __ldg(&s2b[e[m]]);
        ev = ev > 0.f ? ev : ALPHA * ev;
        bool dup = false;
        #pragma unroll
        for (int n = 0; n < m; n++) dup = dup || (e[n] == e[m]);
        w[m] = dup ? -1e30f : ev;
        mx = fmaxf(mx, w[m]);
    }
    float den = 0.f;
    #pragma unroll
    for (int m = 0; m < DEG; m++) {
        w[m] = (w[m] == -1e30f) ? 0.f : __expf(w[m] - mx);
        den += w[m];
    }
    const float inv = 1.f / den;

    ((float4*)g_w)[2 * g]     = make_float4(w[0] * inv, w[1] * inv, w[2] * inv, w[3] * inv);
    ((float4*)g_w)[2 * g + 1] = make_float4(w[4] * inv, w[5] * inv, w[6] * inv, w[7] * inv);
}

// ---------------------------------------------------------------------------
// Kernel 3 (R13, proven): aggregation, two rows per warp (16 gathers inflight).
// ---------------------------------------------------------------------------
__global__ __launch_bounds__(256) void gat_agg(const int* __restrict__ edges,
                                               float* __restrict__ out,
                                               int rowOff)
{
    const int wid  = (blockIdx.x * 256 + threadIdx.x) >> 5;
    const int lane = threadIdx.x & 31;
    const int g0   = rowOff + wid * 2;
    const int b    = g0 >> 10;

    const __half2* hb = g_h2 + ((size_t)b << 15);

    const float4 wa0 = __ldg(&((const float4*)g_w)[2 * g0]);
    const float4 wb0 = __ldg(&((const float4*)g_w)[2 * g0 + 1]);
    const float4 wa1 = __ldg(&((const float4*)g_w)[2 * g0 + 2]);
    const float4 wb1 = __ldg(&((const float4*)g_w)[2 * g0 + 3]);
    const int4 ea0 = __ldg(&((const int4*)edges)[2 * g0]);
    const int4 eb0 = __ldg(&((const int4*)edges)[2 * g0 + 1]);
    const int4 ea1 = __ldg(&((const int4*)edges)[2 * g0 + 2]);
    const int4 eb1 = __ldg(&((const int4*)edges)[2 * g0 + 3]);

    float2 acc0 = make_float2(0.f, 0.f);
    float2 acc1 = make_float2(0.f, 0.f);
    #define GSTEP(ACC, E, Wv) { \
        const float2 hv = __half22float2(__ldg(&hb[(size_t)((E) & (Nn - 1)) * 32 + lane])); \
        ACC.x = fmaf((Wv), hv.x, ACC.x); \
        ACC.y = fmaf((Wv), hv.y, ACC.y); }
    GSTEP(acc0, ea0.x, wa0.x) GSTEP(acc1, ea1.x, wa1.x)
    GSTEP(acc0, ea0.y, wa0.y) GSTEP(acc1, ea1.y, wa1.y)
    GSTEP(acc0, ea0.z, wa0.z) GSTEP(acc1, ea1.z, wa1.z)
    GSTEP(acc0, ea0.w, wa0.w) GSTEP(acc1, ea1.w, wa1.w)
    GSTEP(acc0, eb0.x, wb0.x) GSTEP(acc1, eb1.x, wb1.x)
    GSTEP(acc0, eb0.y, wb0.y) GSTEP(acc1, eb1.y, wb1.y)
    GSTEP(acc0, eb0.z, wb0.z) GSTEP(acc1, eb1.z, wb1.z)
    GSTEP(acc0, eb0.w, wb0.w) GSTEP(acc1, eb1.w, wb1.w)
    #undef GSTEP

    float2 o0, o1;
    o0.x = acc0.x > 0.f ? acc0.x : (__expf(acc0.x) - 1.f);
    o0.y = acc0.y > 0.f ? acc0.y : (__expf(acc0.y) - 1.f);
    o1.x = acc1.x > 0.f ? acc1.x : (__expf(acc1.x) - 1.f);
    o1.y = acc1.y > 0.f ? acc1.y : (__expf(acc1.y) - 1.f);
    ((float2*)out)[(size_t)g0 * 32 + lane]       = o0;
    ((float2*)out)[(size_t)(g0 + 1) * 32 + lane] = o1;
}

// ---------------------------------------------------------------------------
extern "C" void kernel_launch(void* const* d_in, const int* in_sizes, int n_in,
                              void* d_out, int out_size) {
    // Bind inputs BY ELEMENT COUNT (all four sizes distinct) — order-proof.
    const float* atoms = nullptr;   // 64*1024*64 = 4194304 (f32)
    const int*   edges = nullptr;   // 64*1024*8  = 524288  (i32: jax x64 off)
    const float* W     = nullptr;   // 64*64      = 4096    (f32)
    const float* a     = nullptr;   // 2*64*1     = 128     (f32)

    for (int i = 0; i < n_in; i++) {
        switch (in_sizes[i]) {
            case 4194304: atoms = (const float*)d_in[i]; break;
            case 524288:  edges = (const int*)d_in[i];   break;
            case 4096:    W     = (const float*)d_in[i]; break;
            case 128:     a     = (const float*)d_in[i]; break;
            default: break;
        }
    }
    if (!atoms || !edges || !W || !a) return;

    float* out = (float*)d_out;

    const int smem = (64 * SAT_PITCH + 64 * 64) * sizeof(float);  // 82944 B
    cudaFuncSetAttribute(gat_gemm, cudaFuncAttributeMaxDynamicSharedMemorySize, smem);

    // One-time resources (host-side handles only; no device memory).
    static cudaStream_t s2 = nullptr;
    static cudaEvent_t  evFork = nullptr, evJoin = nullptr;
    if (!s2) {
        cudaStreamCreateWithFlags(&s2, cudaStreamNonBlocking);
        cudaEventCreateWithFlags(&evFork, cudaEventDisableTiming);
        cudaEventCreateWithFlags(&evJoin, cudaEventDisableTiming);
    }

    // stream0: gemm half0 -> gemm half1 -> tail half1
    // s2:      (after gemm half0) tail half0   [overlaps gemm half1]
    gat_gemm<<<HALF_ROWS / 256, 256, smem>>>(atoms, W, a, 0);
    cudaEventRecord(evFork, 0);

    gat_gemm<<<HALF_ROWS / 256, 256, smem>>>(atoms, W, a, HALF_ROWS);

    cudaStreamWaitEvent(s2, evFork, 0);
    gat_weights<<<HALF_ROWS / 256, 256, 0, s2>>>(edges, 0);
    gat_agg<<<HALF_ROWS / 2 / 8, 256, 0, s2>>>(edges, out, 0);
    cudaEventRecord(evJoin, s2);

    gat_weights<<<HALF_ROWS / 256, 256>>>(edges, HALF_ROWS);
    gat_agg<<<HALF_ROWS / 2 / 8, 256>>>(edges, out, HALF_ROWS);

    cudaStreamWaitEvent(0, evJoin, 0);   // join s2 back into the capture stream
}